// round 2
// baseline (speedup 1.0000x reference)
#include <cuda_runtime.h>
#include <cstdint>

#define NTRI 300000
#define NN   50000
#define NRLS 50
#define RPD  16
#define EMB  16
#define NC   10
#define EPSV 1e-6f

// ---------------- scratch (device globals; no allocation allowed) ----------------
__device__ float g_lat1[NTRI * RPD];        // 19.2 MB  lat1[t][j]
__device__ float g_lat2[NTRI * RPD];        // 19.2 MB  relu(lat2)[t][j]
__device__ int   g_cnt[2 * NN];             // [0,NN) subj counts, [NN,2NN) obj counts
__device__ int   g_cur[2 * NN];             // fill cursors
__device__ int   g_offs[2 * (NN + 1)];      // subj offs [0..NN], obj offs [NN+1..2NN+1]
__device__ int   g_csr_s[NTRI];
__device__ int   g_csr_o[NTRI];
__device__ float g_S[NN * RPD];             // per-object sums of lat1
__device__ float g_T[NN * RPD];             // per-subject sums of lat2
__device__ float g_colsum[NN * RPD];        // dense colsum (layer 1 norm)
__device__ float g_rowsum[NN * RPD];        // dense rowsum (layer 2 norm)
__device__ float g_h[NN * EMB];             // layer-1 output
__device__ float g_D[NN * 15 * NC];         // 30 MB: per-(s,j>=1) logits contribution
__device__ float g_j0sum1;                  // sum_t lat1[t][0]
__device__ float g_j0sum2;                  // sum_t lat2[t][0]
__device__ float g_J0[EMB];                 // sum_t lat2[t][0]*h[o_t]

// ---------------- K1: zero counters ----------------
__global__ void k_init() {
    int i = blockIdx.x * blockDim.x + threadIdx.x;
    if (i < 2 * NN) { g_cnt[i] = 0; g_cur[i] = 0; }
    if (i < EMB) g_J0[i] = 0.f;
    if (i == 0) { g_j0sum1 = 0.f; g_j0sum2 = 0.f; }
}

// ---------------- K2: latents (both layers), histogram, j0 sums ----------------
#define LAT_TB 128
__global__ void k_lat(const float* __restrict__ nhots,
                      const int* __restrict__ hrow,
                      const int* __restrict__ vcol,
                      const float* __restrict__ Wl1, const float* __restrict__ bl1,
                      const float* __restrict__ Wl2, const float* __restrict__ bl2) {
    __shared__ float shn[LAT_TB * NRLS];       // 25.6 KB
    __shared__ float shW1[NRLS * RPD];
    __shared__ float shW2[NRLS * RPD];
    __shared__ float shb[2 * RPD];
    int tid = threadIdx.x;
    for (int i = tid; i < NRLS * RPD; i += LAT_TB) { shW1[i] = Wl1[i]; shW2[i] = Wl2[i]; }
    if (tid < RPD) { shb[tid] = bl1[tid]; shb[RPD + tid] = bl2[tid]; }
    int base = blockIdx.x * LAT_TB;
    for (int i = tid; i < LAT_TB * NRLS; i += LAT_TB) {
        int tt = base + i / NRLS;
        shn[i] = (tt < NTRI) ? nhots[base * NRLS + i] : 0.f;
    }
    __syncthreads();

    float j0a = 0.f, j0b = 0.f;
    int t = base + tid;
    if (t < NTRI) {
        float z1[RPD], z2[RPD];
#pragma unroll
        for (int j = 0; j < RPD; j++) { z1[j] = shb[j]; z2[j] = shb[RPD + j]; }
        const float* row = shn + tid * NRLS;
        for (int r = 0; r < NRLS; r++) {
            float v = row[r];
            if (v != 0.f) {   // exact: zero entries contribute exactly 0
#pragma unroll
                for (int j = 0; j < RPD; j++) {
                    z1[j] += v * shW1[r * RPD + j];
                    z2[j] += v * shW2[r * RPD + j];
                }
            }
        }
        float m1 = z1[0], m2 = z2[0];
#pragma unroll
        for (int j = 1; j < RPD; j++) { m1 = fmaxf(m1, z1[j]); m2 = fmaxf(m2, z2[j]); }
        float s1 = 0.f, s2 = 0.f;
#pragma unroll
        for (int j = 0; j < RPD; j++) {
            z1[j] = __expf(z1[j] - m1); s1 += z1[j];
            z2[j] = __expf(z2[j] - m2); s2 += z2[j];
        }
        float r1 = 1.f / s1, r2 = 1.f / s2;
#pragma unroll
        for (int j = 0; j < RPD; j++) {
            float a = z1[j] * r1;
            float b = fmaxf(z2[j] * r2, 0.f);   // LACT = relu (no-op for softmax, kept exact)
            g_lat1[t * RPD + j] = a;
            g_lat2[t * RPD + j] = b;
            if (j == 0) { j0a = a; j0b = b; }
        }
        int s = hrow[t], o = vcol[t];
        atomicAdd(&g_cnt[s], 1);
        atomicAdd(&g_cnt[NN + o], 1);
    }
    // warp reduce j0 contributions -> 2 atomics per warp
#pragma unroll
    for (int d = 16; d > 0; d >>= 1) {
        j0a += __shfl_down_sync(0xffffffffu, j0a, d);
        j0b += __shfl_down_sync(0xffffffffu, j0b, d);
    }
    if ((tid & 31) == 0) {
        atomicAdd(&g_j0sum1, j0a);
        atomicAdd(&g_j0sum2, j0b);
    }
}

// ---------------- K3: exclusive scan of counts (2 blocks: subj, obj) ----------------
__global__ void k_scan() {
    __shared__ int wsum[32];
    __shared__ int woff[33];
    int which = blockIdx.x;
    const int* cnt = g_cnt + which * NN;
    int* offs = g_offs + which * (NN + 1);
    int tid = threadIdx.x, lane = tid & 31, wid = tid >> 5;
    int carry = 0;
    for (int base = 0; base < NN; base += 1024) {
        int i = base + tid;
        int x = (i < NN) ? cnt[i] : 0;
        int inc = x;
#pragma unroll
        for (int d = 1; d < 32; d <<= 1) {
            int v = __shfl_up_sync(0xffffffffu, inc, d);
            if (lane >= d) inc += v;
        }
        if (lane == 31) wsum[wid] = inc;
        __syncthreads();
        if (wid == 0) {
            int sc = wsum[lane];
#pragma unroll
            for (int d = 1; d < 32; d <<= 1) {
                int u = __shfl_up_sync(0xffffffffu, sc, d);
                if (lane >= d) sc += u;
            }
            woff[lane + 1] = sc;
            if (lane == 0) woff[0] = 0;
        }
        __syncthreads();
        if (i < NN) offs[i] = carry + woff[wid] + inc - x;
        carry += woff[32];
        __syncthreads();
    }
    if (tid == 0) offs[NN] = carry;
}

// ---------------- K4: fill CSR ----------------
__global__ void k_fill(const int* __restrict__ hrow, const int* __restrict__ vcol) {
    int t = blockIdx.x * blockDim.x + threadIdx.x;
    if (t >= NTRI) return;
    int s = hrow[t], o = vcol[t];
    int ps = atomicAdd(&g_cur[s], 1);
    g_csr_s[g_offs[s] + ps] = t;
    int po = atomicAdd(&g_cur[NN + o], 1);
    g_csr_o[g_offs[NN + 1 + o] + po] = t;
}

// ---------------- K5: per-group 16-vector sums (half-warp per group) ----------------
__global__ void k_groupsum() {
    int gid = blockIdx.x * (blockDim.x >> 4) + (threadIdx.x >> 4);
    int lane16 = threadIdx.x & 15;
    if (gid < NN) {                      // subject -> T (lat2)
        int s = gid;
        int beg = g_offs[s], end = g_offs[s + 1];
        float acc = 0.f;
        for (int p = beg; p < end; p++) {
            int t = g_csr_s[p];
            acc += g_lat2[t * RPD + lane16];
        }
        g_T[s * RPD + lane16] = acc;
    } else if (gid < 2 * NN) {           // object -> S (lat1)
        int o = gid - NN;
        int beg = g_offs[NN + 1 + o], end = g_offs[NN + 1 + o + 1];
        float acc = 0.f;
        for (int p = beg; p < end; p++) {
            int t = g_csr_o[p];
            acc += g_lat1[t * RPD + lane16];
        }
        g_S[o * RPD + lane16] = acc;
    }
}

// ---------------- K6: dense colsum/rowsum via divisor enumeration ----------------
__global__ void k_sumbuild() {
    int k = blockIdx.x * blockDim.x + threadIdx.x;
    if (k >= NN * RPD) return;
    float cs = 0.f, rs = 0.f;
    if (k == 0) { cs = g_j0sum1; rs = g_j0sum2; }
#pragma unroll
    for (int j = 1; j < RPD; j++) {
        unsigned s = (unsigned)k / (unsigned)j;
        if (s * (unsigned)j == (unsigned)k && s < NN) {
            cs += g_S[s * RPD + j];
            rs += g_T[s * RPD + j];
        }
    }
    g_colsum[k] = cs;
    g_rowsum[k] = rs;
}

// ---------------- K7: layer-1 h[s] (warp per subject, no atomics) ----------------
__global__ void k_layer1(const int* __restrict__ vcol,
                         const float* __restrict__ W1,
                         const float* __restrict__ bias1) {
    int warp = threadIdx.x >> 5;
    int s = blockIdx.x * 8 + warp;
    int lane = threadIdx.x & 31;
    int half = lane >> 4, e = lane & 15;
    float acc = 0.f;
    int beg = g_offs[s], end = g_offs[s + 1];
    for (int p = beg; p < end; p++) {
        int t = g_csr_s[p];
        int o = vcol[t];
#pragma unroll
        for (int jj = 0; jj < 8; jj++) {
            int j = half + 2 * jj;
            int idx = o * j;
            float a = g_lat1[t * RPD + j];
            float c = g_colsum[idx];
            acc += (a / fmaxf(c, EPSV)) * W1[idx * EMB + e];
        }
    }
    acc += __shfl_xor_sync(0xffffffffu, acc, 16);
    if (lane < 16) g_h[s * EMB + lane] = fmaxf(acc + bias1[lane], 0.f);
}

// ---------------- K8: layer-2 outer products + folded W2 matvec -> D ----------------
__global__ void k_layer2(const int* __restrict__ vcol,
                         const float* __restrict__ W2) {
    __shared__ float shW2[RPD * EMB * NC];   // 10 KB
    __shared__ float shC[8 * 256];           // 8 KB
    __shared__ float shJ0[EMB];
    int tid = threadIdx.x;
    for (int i = tid; i < RPD * EMB * NC; i += 256) shW2[i] = W2[i];
    if (tid < EMB) shJ0[tid] = 0.f;
    __syncthreads();

    int warp = tid >> 5, lane = tid & 31;
    int half = lane >> 4, e = lane & 15;
    int s = blockIdx.x * 8 + warp;
    float acc[8];
#pragma unroll
    for (int k = 0; k < 8; k++) acc[k] = 0.f;

    int beg = g_offs[s], end = g_offs[s + 1];
    for (int p = beg; p < end; p++) {
        int t = g_csr_s[p];
        int o = vcol[t];
        float hv = g_h[o * EMB + e];
        float lv = (lane < 16) ? g_lat2[t * RPD + lane] : 0.f;
#pragma unroll
        for (int k = 0; k < 8; k++) {
            float a = __shfl_sync(0xffffffffu, lv, half + 2 * k);
            acc[k] += a * hv;       // C[j=half+2k][e]
        }
    }
    float* Cw = shC + warp * 256;
#pragma unroll
    for (int k = 0; k < 8; k++) Cw[(half + 2 * k) * EMB + e] = acc[k];
    __syncwarp();
    if (half == 0) atomicAdd(&shJ0[e], acc[0]);   // j=0 component (shared atomic)

    // 15 j's x 10 c's = 150 tasks across the warp
    for (int id = lane; id < 150; id += 32) {
        int j = 1 + id / 10;
        int c = id - (j - 1) * 10;
        int idx = s * j;
        int r = idx / NN;
        float scale = 1.f / fmaxf(g_rowsum[idx], EPSV);
        float v = 0.f;
#pragma unroll
        for (int e2 = 0; e2 < EMB; e2++)
            v += Cw[j * EMB + e2] * shW2[(r * EMB + e2) * NC + c];
        g_D[(s * 15 + (j - 1)) * NC + c] = v * scale;
    }
    __syncthreads();
    if (tid < EMB) atomicAdd(&g_J0[tid], shJ0[tid]);
}

// ---------------- K9: gather D by divisor enumeration -> logits ----------------
__global__ void k_out(float* __restrict__ out,
                      const float* __restrict__ W2,
                      const float* __restrict__ bias2) {
    int i = blockIdx.x * blockDim.x + threadIdx.x;
    if (i >= NN) return;
    float a[NC];
#pragma unroll
    for (int c = 0; c < NC; c++) a[c] = bias2[c];
#pragma unroll
    for (int j = 1; j < RPD; j++) {
#pragma unroll
        for (int r = 0; r < RPD; r++) {
            unsigned k = (unsigned)(r * NN + i);
            unsigned s = k / (unsigned)j;       // const division (unrolled j)
            if (s * (unsigned)j == k && s < NN) {
                const float* d = g_D + (s * 15 + (j - 1)) * NC;
#pragma unroll
                for (int c = 0; c < NC; c++) a[c] += d[c];
            }
        }
    }
    if (i == 0) {   // global j=0 term: (J0/clip(rowsum[0])) @ W2[r=0]
        float inv = 1.f / fmaxf(g_rowsum[0], EPSV);
#pragma unroll
        for (int c = 0; c < NC; c++) {
            float v = 0.f;
#pragma unroll
            for (int e2 = 0; e2 < EMB; e2++) v += g_J0[e2] * W2[e2 * NC + c];
            a[c] += v * inv;
        }
    }
#pragma unroll
    for (int c = 0; c < NC; c++) out[i * NC + c] = a[c];
}

// ---------------- launcher ----------------
extern "C" void kernel_launch(void* const* d_in, const int* in_sizes, int n_in,
                              void* d_out, int out_size) {
    const float* nhots = (const float*)d_in[0];
    const int*   hrow  = (const int*)d_in[1];   // hrow[t] = s_t for t < NT
    const int*   vcol  = (const int*)d_in[4];   // vcol[t] = o_t for t < NT
    const float* Wl1   = (const float*)d_in[5];
    const float* bl1   = (const float*)d_in[6];
    const float* Wl2   = (const float*)d_in[7];
    const float* bl2   = (const float*)d_in[8];
    const float* W1    = (const float*)d_in[9];
    const float* b1    = (const float*)d_in[10];
    const float* W2    = (const float*)d_in[11];
    const float* b2    = (const float*)d_in[12];
    float* out = (float*)d_out;
    (void)in_sizes; (void)n_in; (void)out_size;

    k_init<<<(2 * NN + 255) / 256, 256>>>();
    k_lat<<<(NTRI + LAT_TB - 1) / LAT_TB, LAT_TB>>>(nhots, hrow, vcol, Wl1, bl1, Wl2, bl2);
    k_scan<<<2, 1024>>>();
    k_fill<<<(NTRI + 255) / 256, 256>>>(hrow, vcol);
    k_groupsum<<<(2 * NN) / 16, 256>>>();
    k_sumbuild<<<(NN * RPD + 255) / 256, 256>>>();
    k_layer1<<<NN / 8, 256>>>(vcol, W1, b1);
    k_layer2<<<NN / 8, 256>>>(vcol, W2);
    k_out<<<(NN + 255) / 256, 256>>>(out, W2, b2);
}

// round 3
// speedup vs baseline: 1.4660x; 1.4660x over previous
#include <cuda_runtime.h>
#include <cstdint>

#define NTRI 300000
#define NN   50000
#define NRLS 50
#define RPD  16
#define EMB  16
#define NC   10
#define EPSV 1e-6f

// ---------------- scratch (device globals; no allocation allowed) ----------------
__device__ int   g_p[NTRI];                 // relation id per triple
__device__ int   g_pcnt[NRLS];              // relation histogram
__device__ float g_tab1[NRLS * RPD];        // softmax(Wl1[p]+bl1)
__device__ float g_tab2[NRLS * RPD];        // relu(softmax(Wl2[p]+bl2))
__device__ int   g_cnt[2 * NN];             // [0,NN) subj counts, [NN,2NN) obj counts
__device__ int   g_cur[2 * NN];             // fill cursors (pre-seeded with offsets)
__device__ int   g_offs[2 * (NN + 1)];      // subj offs [0..NN], obj offs [NN+1..2NN+1]
__device__ int   g_csr_s[NTRI];
__device__ int   g_csr_o[NTRI];
__device__ float g_S[NN * RPD];             // per-object sums of lat1
__device__ float g_T[NN * RPD];             // per-subject sums of lat2
__device__ float g_cinv[NN * RPD];          // 1/clip(colsum)  (layer 1 norm)
__device__ float g_rinv[NN * RPD];          // 1/clip(rowsum)  (layer 2 norm)
__device__ float g_h[NN * EMB];             // layer-1 output
__device__ float g_D[NN * 15 * NC];         // per-(s,j>=1) logits contribution
__device__ float g_j0sum1;                  // sum_t tab1[p_t][0]
__device__ float g_j0sum2;                  // sum_t tab2[p_t][0]
__device__ float g_J0[EMB];                 // sum_t tab2[p_t][0]*h[o_t]

// ---------------- K1: zero counters ----------------
__global__ void k_init() {
    int i = blockIdx.x * blockDim.x + threadIdx.x;
    if (i < 2 * NN) g_cnt[i] = 0;
    if (i < NRLS) g_pcnt[i] = 0;
    if (i < EMB) g_J0[i] = 0.f;
}

// ---------------- K2: find relation id per triple + histograms ----------------
#define FP_TB 128
__global__ void k_findp(const float* __restrict__ nhots,
                        const int* __restrict__ hrow,
                        const int* __restrict__ vcol) {
    __shared__ float shn[FP_TB * NRLS];   // 25.6 KB staged one-hot rows
    __shared__ int shp[NRLS];
    int tid = threadIdx.x;
    if (tid < NRLS) shp[tid] = 0;
    int base = blockIdx.x * FP_TB;
    for (int i = tid; i < FP_TB * NRLS; i += FP_TB) {
        int tt = base + i / NRLS;
        shn[i] = (tt < NTRI) ? nhots[base * NRLS + i] : 0.f;
    }
    __syncthreads();
    int t = base + tid;
    if (t < NTRI) {
        const float* row = shn + tid * NRLS;
        int p = 0;
        for (int r = 0; r < NRLS; r++) {
            if (row[r] != 0.f) { p = r; break; }
        }
        g_p[t] = p;
        atomicAdd(&shp[p], 1);
        atomicAdd(&g_cnt[hrow[t]], 1);
        atomicAdd(&g_cnt[NN + vcol[t]], 1);
    }
    __syncthreads();
    if (tid < NRLS && shp[tid]) atomicAdd(&g_pcnt[tid], shp[tid]);
}

// ---------------- K3: 50-row softmax tables + j0 global sums ----------------
__global__ void k_tables(const float* __restrict__ Wl1, const float* __restrict__ bl1,
                         const float* __restrict__ Wl2, const float* __restrict__ bl2) {
    int p = threadIdx.x;
    if (p < NRLS) {
        float z1[RPD], z2[RPD];
        float m1 = -1e30f, m2 = -1e30f;
#pragma unroll
        for (int j = 0; j < RPD; j++) {
            z1[j] = Wl1[p * RPD + j] + bl1[j];
            z2[j] = Wl2[p * RPD + j] + bl2[j];
            m1 = fmaxf(m1, z1[j]); m2 = fmaxf(m2, z2[j]);
        }
        float s1 = 0.f, s2 = 0.f;
#pragma unroll
        for (int j = 0; j < RPD; j++) {
            z1[j] = __expf(z1[j] - m1); s1 += z1[j];
            z2[j] = __expf(z2[j] - m2); s2 += z2[j];
        }
        float r1 = 1.f / s1, r2 = 1.f / s2;
#pragma unroll
        for (int j = 0; j < RPD; j++) {
            g_tab1[p * RPD + j] = z1[j] * r1;
            g_tab2[p * RPD + j] = fmaxf(z2[j] * r2, 0.f);  // LACT = relu
        }
    }
    __syncthreads();
    if (p == 0) {
        float a = 0.f, b = 0.f;
        for (int q = 0; q < NRLS; q++) {
            float c = (float)g_pcnt[q];
            a += c * g_tab1[q * RPD];
            b += c * g_tab2[q * RPD];
        }
        g_j0sum1 = a; g_j0sum2 = b;
    }
}

// ---------------- K4: exclusive scan of counts (2 blocks: subj, obj) ----------------
__global__ void k_scan() {
    __shared__ int wsum[32];
    __shared__ int woff[33];
    int which = blockIdx.x;
    const int* cnt = g_cnt + which * NN;
    int* offs = g_offs + which * (NN + 1);
    int* cur  = g_cur + which * NN;
    int tid = threadIdx.x, lane = tid & 31, wid = tid >> 5;
    int carry = 0;
    for (int base = 0; base < NN; base += 1024) {
        int i = base + tid;
        int x = (i < NN) ? cnt[i] : 0;
        int inc = x;
#pragma unroll
        for (int d = 1; d < 32; d <<= 1) {
            int v = __shfl_up_sync(0xffffffffu, inc, d);
            if (lane >= d) inc += v;
        }
        if (lane == 31) wsum[wid] = inc;
        __syncthreads();
        if (wid == 0) {
            int sc = wsum[lane];
#pragma unroll
            for (int d = 1; d < 32; d <<= 1) {
                int u = __shfl_up_sync(0xffffffffu, sc, d);
                if (lane >= d) sc += u;
            }
            woff[lane + 1] = sc;
            if (lane == 0) woff[0] = 0;
        }
        __syncthreads();
        if (i < NN) {
            int off = carry + woff[wid] + inc - x;
            offs[i] = off;
            cur[i] = off;          // pre-seed cursor with offset
        }
        carry += woff[32];
        __syncthreads();
    }
    if (tid == 0) offs[NN] = carry;
}

// ---------------- K5: fill CSR (cursor already holds base offset) ----------------
__global__ void k_fill(const int* __restrict__ hrow, const int* __restrict__ vcol) {
    int t = blockIdx.x * blockDim.x + threadIdx.x;
    if (t >= NTRI) return;
    int s = hrow[t], o = vcol[t];
    int ps = atomicAdd(&g_cur[s], 1);
    g_csr_s[ps] = t;
    int po = atomicAdd(&g_cur[NN + o], 1);
    g_csr_o[po] = t;
}

// ---------------- K6: per-group 16-vector sums via relation table ----------------
__global__ void k_groupsum() {
    __shared__ float sh1[NRLS * RPD];
    __shared__ float sh2[NRLS * RPD];
    for (int i = threadIdx.x; i < NRLS * RPD; i += blockDim.x) {
        sh1[i] = g_tab1[i]; sh2[i] = g_tab2[i];
    }
    __syncthreads();
    int gid = blockIdx.x * (blockDim.x >> 4) + (threadIdx.x >> 4);
    int lane16 = threadIdx.x & 15;
    if (gid < NN) {                      // subject -> T (lat2)
        int s = gid;
        int beg = g_offs[s], end = g_offs[s + 1];
        float acc = 0.f;
        for (int p = beg; p < end; p++) {
            int t = g_csr_s[p];
            acc += sh2[g_p[t] * RPD + lane16];
        }
        g_T[s * RPD + lane16] = acc;
    } else if (gid < 2 * NN) {           // object -> S (lat1)
        int o = gid - NN;
        int beg = g_offs[NN + 1 + o], end = g_offs[NN + 1 + o + 1];
        float acc = 0.f;
        for (int p = beg; p < end; p++) {
            int t = g_csr_o[p];
            acc += sh1[g_p[t] * RPD + lane16];
        }
        g_S[o * RPD + lane16] = acc;
    }
}

// ---------------- K7: dense colsum/rowsum via divisor enumeration -> reciprocals ----------------
__global__ void k_sumbuild() {
    int k = blockIdx.x * blockDim.x + threadIdx.x;
    if (k >= NN * RPD) return;
    float cs = 0.f, rs = 0.f;
    if (k == 0) { cs = g_j0sum1; rs = g_j0sum2; }
#pragma unroll
    for (int j = 1; j < RPD; j++) {
        unsigned s = (unsigned)k / (unsigned)j;
        if (s * (unsigned)j == (unsigned)k && s < NN) {
            cs += g_S[s * RPD + j];
            rs += g_T[s * RPD + j];
        }
    }
    g_cinv[k] = 1.f / fmaxf(cs, EPSV);
    g_rinv[k] = 1.f / fmaxf(rs, EPSV);
}

// ---------------- K8: layer-1 h[s] (warp per subject, no atomics) ----------------
__global__ void k_layer1(const int* __restrict__ vcol,
                         const float* __restrict__ W1,
                         const float* __restrict__ bias1) {
    __shared__ float sh1[NRLS * RPD];
    for (int i = threadIdx.x; i < NRLS * RPD; i += blockDim.x) sh1[i] = g_tab1[i];
    __syncthreads();
    int warp = threadIdx.x >> 5;
    int s = blockIdx.x * 8 + warp;
    int lane = threadIdx.x & 31;
    int half = lane >> 4, e = lane & 15;
    float acc = 0.f;
    int beg = g_offs[s], end = g_offs[s + 1];
    for (int p = beg; p < end; p++) {
        int t = g_csr_s[p];
        int o = vcol[t];
        int pt = g_p[t];
#pragma unroll
        for (int jj = 0; jj < 8; jj++) {
            int j = half + 2 * jj;
            int idx = o * j;
            acc += sh1[pt * RPD + j] * g_cinv[idx] * W1[idx * EMB + e];
        }
    }
    acc += __shfl_xor_sync(0xffffffffu, acc, 16);
    if (lane < 16) g_h[s * EMB + lane] = fmaxf(acc + bias1[lane], 0.f);
}

// ---------------- K9: layer-2 outer products + folded W2 matvec -> D ----------------
__global__ void k_layer2(const int* __restrict__ vcol,
                         const float* __restrict__ W2) {
    __shared__ float shW2[RPD * EMB * NC];   // 10 KB
    __shared__ float shC[8 * 256];           // 8 KB
    __shared__ float sh2[NRLS * RPD];        // 3.2 KB
    __shared__ float shJ0[EMB];
    int tid = threadIdx.x;
    for (int i = tid; i < RPD * EMB * NC; i += 256) shW2[i] = W2[i];
    for (int i = tid; i < NRLS * RPD; i += 256) sh2[i] = g_tab2[i];
    if (tid < EMB) shJ0[tid] = 0.f;
    __syncthreads();

    int warp = tid >> 5, lane = tid & 31;
    int half = lane >> 4, e = lane & 15;
    int s = blockIdx.x * 8 + warp;
    float acc[8];
#pragma unroll
    for (int k = 0; k < 8; k++) acc[k] = 0.f;

    int beg = g_offs[s], end = g_offs[s + 1];
    for (int p = beg; p < end; p++) {
        int t = g_csr_s[p];
        int o = vcol[t];
        int pt = g_p[t];
        float hv = g_h[o * EMB + e];
        float lv = (lane < 16) ? sh2[pt * RPD + lane] : 0.f;
#pragma unroll
        for (int k = 0; k < 8; k++) {
            float a = __shfl_sync(0xffffffffu, lv, half + 2 * k);
            acc[k] += a * hv;       // C[j=half+2k][e]
        }
    }
    float* Cw = shC + warp * 256;
#pragma unroll
    for (int k = 0; k < 8; k++) Cw[(half + 2 * k) * EMB + e] = acc[k];
    __syncwarp();
    if (half == 0) atomicAdd(&shJ0[e], acc[0]);   // j=0 component (shared atomic)

    // 15 j's x 10 c's = 150 tasks across the warp
    for (int id = lane; id < 150; id += 32) {
        int j = 1 + id / 10;
        int c = id - (j - 1) * 10;
        int idx = s * j;
        int r = idx / NN;
        float scale = g_rinv[idx];
        float v = 0.f;
#pragma unroll
        for (int e2 = 0; e2 < EMB; e2++)
            v += Cw[j * EMB + e2] * shW2[(r * EMB + e2) * NC + c];
        g_D[(s * 15 + (j - 1)) * NC + c] = v * scale;
    }
    __syncthreads();
    if (tid < EMB) atomicAdd(&g_J0[tid], shJ0[tid]);
}

// ---------------- K10: gather D by divisor enumeration -> logits ----------------
__global__ void k_out(float* __restrict__ out,
                      const float* __restrict__ W2,
                      const float* __restrict__ bias2) {
    int i = blockIdx.x * blockDim.x + threadIdx.x;
    if (i >= NN) return;
    float a[NC];
#pragma unroll
    for (int c = 0; c < NC; c++) a[c] = bias2[c];
#pragma unroll
    for (int j = 1; j < RPD; j++) {
#pragma unroll
        for (int r = 0; r < RPD; r++) {
            unsigned k = (unsigned)(r * NN + i);
            unsigned s = k / (unsigned)j;       // const division (unrolled j)
            if (s * (unsigned)j == k && s < NN) {
                const float* d = g_D + (s * 15 + (j - 1)) * NC;
#pragma unroll
                for (int c = 0; c < NC; c++) a[c] += d[c];
            }
        }
    }
    if (i == 0) {   // global j=0 term: (J0 * rinv[0]) @ W2[r=0]
        float inv = g_rinv[0];
#pragma unroll
        for (int c = 0; c < NC; c++) {
            float v = 0.f;
#pragma unroll
            for (int e2 = 0; e2 < EMB; e2++) v += g_J0[e2] * W2[e2 * NC + c];
            a[c] += v * inv;
        }
    }
#pragma unroll
    for (int c = 0; c < NC; c++) out[i * NC + c] = a[c];
}

// ---------------- launcher ----------------
extern "C" void kernel_launch(void* const* d_in, const int* in_sizes, int n_in,
                              void* d_out, int out_size) {
    const float* nhots = (const float*)d_in[0];
    const int*   hrow  = (const int*)d_in[1];   // hrow[t] = s_t for t < NT
    const int*   vcol  = (const int*)d_in[4];   // vcol[t] = o_t for t < NT
    const float* Wl1   = (const float*)d_in[5];
    const float* bl1   = (const float*)d_in[6];
    const float* Wl2   = (const float*)d_in[7];
    const float* bl2   = (const float*)d_in[8];
    const float* W1    = (const float*)d_in[9];
    const float* b1    = (const float*)d_in[10];
    const float* W2    = (const float*)d_in[11];
    const float* b2    = (const float*)d_in[12];
    float* out = (float*)d_out;
    (void)in_sizes; (void)n_in; (void)out_size;

    k_init<<<(2 * NN + 255) / 256, 256>>>();
    k_findp<<<(NTRI + FP_TB - 1) / FP_TB, FP_TB>>>(nhots, hrow, vcol);
    k_tables<<<1, 64>>>(Wl1, bl1, Wl2, bl2);
    k_scan<<<2, 1024>>>();
    k_fill<<<(NTRI + 255) / 256, 256>>>(hrow, vcol);
    k_groupsum<<<(2 * NN) / 16, 256>>>();
    k_sumbuild<<<(NN * RPD + 255) / 256, 256>>>();
    k_layer1<<<NN / 8, 256>>>(vcol, W1, b1);
    k_layer2<<<NN / 8, 256>>>(vcol, W2);
    k_out<<<(NN + 255) / 256, 256>>>(out, W2, b2);
}